// round 2
// baseline (speedup 1.0000x reference)
#include <cuda_runtime.h>
#include <cstdint>

typedef unsigned long long ull;

#define BB 4
#define TT 4096
#define EE 1024
#define DFF 4096
#define NSTEPS 128
#define NROWS 256

__device__ float g_W[64 * 64];
__device__ float g_proc[2][NROWS * EE];
__device__ float g_res2[NROWS * EE];
__device__ float g_cn2[NROWS * EE];
__device__ float g_gv[NROWS * 2 * DFF];
__device__ float g_f[NROWS * DFF];
__device__ float g_part[8][NROWS * EE];
__device__ float g_mu1[NROWS];
__device__ float g_r1[NROWS];

__device__ __forceinline__ ull pack2(float v) {
    ull r; unsigned u = __float_as_uint(v);
    asm("mov.b64 %0, {%1, %1};" : "=l"(r) : "r"(u));
    return r;
}
__device__ __forceinline__ void dfma(ull &c, ull a, ull b) {
    asm("fma.rn.f32x2 %0, %1, %2, %0;" : "+l"(c) : "l"(a), "l"(b));
}

__global__ void k_init_W(const float* __restrict__ wf1, const float* __restrict__ wf2) {
    for (int id = threadIdx.x; id < 64 * 64; id += blockDim.x) {
        int t = id >> 6, tp = id & 63;
        float s = 0.f;
        #pragma unroll
        for (int u = 0; u < 48; ++u) s += wf2[t * 48 + u] * wf1[u * 64 + tp];
        g_W[id] = s;
    }
}

__global__ void k_init_prev(const float* __restrict__ x) {
    int idx = blockIdx.x * blockDim.x + threadIdx.x;  // 0..131071
    int b = idx >> 15, rem = idx & 32767;
    int r = rem >> 10, e = rem & 1023;
    g_proc[0][(size_t)((b << 6) + 32 + r) * EE + e] = x[((size_t)b * TT + r) * EE + e];
}

__global__ __launch_bounds__(128) void k_pre(const float* __restrict__ x, int step) {
    int warp = threadIdx.x >> 5, lane = threadIdx.x & 31;
    int m = blockIdx.x * 4 + warp;
    int b = m >> 6, t = m & 63;
    const float* ptr = nullptr;
    if (t < 32) ptr = g_proc[step & 1] + (size_t)((b << 6) + 32 + t) * EE;
    else { int g = step * 32 + t; if (g < TT) ptr = x + ((size_t)b * TT + g) * EE; }
    float sum = 0.f, sq = 0.f;
    if (ptr) for (int e = lane * 4; e < EE; e += 128) {
        float4 v = *(const float4*)(ptr + e);
        sum += v.x + v.y + v.z + v.w;
        sq += v.x * v.x + v.y * v.y + v.z * v.z + v.w * v.w;
    }
    #pragma unroll
    for (int off = 16; off; off >>= 1) {
        sum += __shfl_xor_sync(~0u, sum, off);
        sq  += __shfl_xor_sync(~0u, sq, off);
    }
    if (lane == 0) {
        float mu = sum * (1.f / 1024.f);
        g_mu1[m] = mu;
        g_r1[m] = rsqrtf(sq * (1.f / 1024.f) - mu * mu + 1e-5f);
    }
}

// res2 = W @ LN1(mixed) + chunk    (per batch b, per embed column e)
__global__ __launch_bounds__(128) void k_fft(const float* __restrict__ x,
                                             const float* __restrict__ w1,
                                             const float* __restrict__ b1, int step) {
    __shared__ __align__(16) float sW[64][64];
    __shared__ float smu[64], sr[64];
    int b = blockIdx.y;
    int e = blockIdx.x * 128 + threadIdx.x;
    for (int id = threadIdx.x; id < 4096; id += 128) ((float*)sW)[id] = g_W[id];
    if (threadIdx.x < 64) {
        smu[threadIdx.x] = g_mu1[(b << 6) + threadIdx.x];
        sr[threadIdx.x]  = g_r1[(b << 6) + threadIdx.x];
    }
    __syncthreads();
    const float* prev = g_proc[step & 1];
    const float* xb = x + (size_t)b * TT * EE;
    float we = w1[e], be = b1[e];
    float cn[64];
    #pragma unroll
    for (int tp = 0; tp < 64; ++tp) {
        float v;
        if (tp < 32) v = prev[(size_t)((b << 6) + 32 + tp) * EE + e];
        else { int g = step * 32 + tp; v = (g < TT) ? xb[(size_t)g * EE + e] : 0.f; }
        cn[tp] = (v - smu[tp]) * sr[tp] * we + be;
    }
    #pragma unroll 1
    for (int t = 0; t < 64; ++t) {
        const float4* wr = (const float4*)sW[t];
        float acc = 0.f;
        #pragma unroll
        for (int q = 0; q < 16; ++q) {
            float4 w = wr[q];
            acc += w.x * cn[4 * q] + w.y * cn[4 * q + 1] + w.z * cn[4 * q + 2] + w.w * cn[4 * q + 3];
        }
        int g = step * 32 + t;
        float cv = (g < TT) ? xb[(size_t)g * EE + e] : 0.f;
        g_res2[(size_t)((b << 6) + t) * EE + e] = acc + cv;
    }
}

__global__ __launch_bounds__(128) void k_ln2(const float* __restrict__ w,
                                             const float* __restrict__ bb) {
    int warp = threadIdx.x >> 5, lane = threadIdx.x & 31;
    int m = blockIdx.x * 4 + warp;
    const float* row = g_res2 + (size_t)m * EE;
    float sum = 0.f, sq = 0.f;
    for (int e = lane * 4; e < EE; e += 128) {
        float4 v = *(const float4*)(row + e);
        sum += v.x + v.y + v.z + v.w;
        sq += v.x * v.x + v.y * v.y + v.z * v.z + v.w * v.w;
    }
    #pragma unroll
    for (int off = 16; off; off >>= 1) {
        sum += __shfl_xor_sync(~0u, sum, off);
        sq  += __shfl_xor_sync(~0u, sq, off);
    }
    float mu = sum * (1.f / 1024.f);
    float r = rsqrtf(sq * (1.f / 1024.f) - mu * mu + 1e-5f);
    float* dst = g_cn2 + (size_t)m * EE;
    for (int e = lane * 4; e < EE; e += 128) {
        float4 v = *(const float4*)(row + e);
        float4 ww = *(const float4*)(w + e);
        float4 bv = *(const float4*)(bb + e);
        float4 o;
        o.x = (v.x - mu) * r * ww.x + bv.x;
        o.y = (v.y - mu) * r * ww.y + bv.y;
        o.z = (v.z - mu) * r * ww.z + bv.z;
        o.w = (v.w - mu) * r * ww.w + bv.w;
        *(float4*)(dst + e) = o;
    }
}

// C[128x128 tile] = A(M x K) * B(N x K)^T (+bias)
__device__ __forceinline__ void gemm_body(const float* __restrict__ A, int lda,
                                          const float* __restrict__ Bm, int ldb,
                                          float* __restrict__ C, int ldc,
                                          int kOff, int ktCount,
                                          const float* __restrict__ bias) {
    __shared__ __align__(16) float As[2][16][132];
    __shared__ __align__(16) float Bs[2][16][132];
    const int tid = threadIdx.x;
    const int n0 = blockIdx.x * 128, m0 = blockIdx.y * 128;
    const int lr = tid >> 2, lk = (tid & 3) << 2;
    const int tx = tid & 15, ty = tid >> 4;
    const float* Ap = A + (size_t)(m0 + lr) * lda + kOff + lk;
    const float* Bp = Bm + (size_t)(n0 + lr) * ldb + kOff + lk;

    float4 a0 = *(const float4*)(Ap);
    float4 a1 = *(const float4*)(Ap + (size_t)64 * lda);
    float4 b0 = *(const float4*)(Bp);
    float4 b1 = *(const float4*)(Bp + (size_t)64 * ldb);

    ull acc[8][4];
    #pragma unroll
    for (int i = 0; i < 8; ++i)
        #pragma unroll
        for (int j = 0; j < 4; ++j) acc[i][j] = 0ull;

    As[0][lk + 0][lr] = a0.x; As[0][lk + 1][lr] = a0.y; As[0][lk + 2][lr] = a0.z; As[0][lk + 3][lr] = a0.w;
    As[0][lk + 0][lr + 64] = a1.x; As[0][lk + 1][lr + 64] = a1.y; As[0][lk + 2][lr + 64] = a1.z; As[0][lk + 3][lr + 64] = a1.w;
    Bs[0][lk + 0][lr] = b0.x; Bs[0][lk + 1][lr] = b0.y; Bs[0][lk + 2][lr] = b0.z; Bs[0][lk + 3][lr] = b0.w;
    Bs[0][lk + 0][lr + 64] = b1.x; Bs[0][lk + 1][lr + 64] = b1.y; Bs[0][lk + 2][lr + 64] = b1.z; Bs[0][lk + 3][lr + 64] = b1.w;
    __syncthreads();

    for (int kt = 0; kt < ktCount; ++kt) {
        const int buf = kt & 1;
        const bool has = (kt + 1) < ktCount;
        if (has) {
            const float* Ap2 = Ap + (kt + 1) * 16;
            const float* Bp2 = Bp + (kt + 1) * 16;
            a0 = *(const float4*)(Ap2);
            a1 = *(const float4*)(Ap2 + (size_t)64 * lda);
            b0 = *(const float4*)(Bp2);
            b1 = *(const float4*)(Bp2 + (size_t)64 * ldb);
        }
        #pragma unroll
        for (int k = 0; k < 16; ++k) {
            float4 va0 = *(const float4*)&As[buf][k][ty * 8];
            float4 va1 = *(const float4*)&As[buf][k][ty * 8 + 4];
            ulonglong2 vb0 = *(const ulonglong2*)&Bs[buf][k][tx * 8];
            ulonglong2 vb1 = *(const ulonglong2*)&Bs[buf][k][tx * 8 + 4];
            ull bv[4] = {vb0.x, vb0.y, vb1.x, vb1.y};
            float av[8] = {va0.x, va0.y, va0.z, va0.w, va1.x, va1.y, va1.z, va1.w};
            #pragma unroll
            for (int i = 0; i < 8; ++i) {
                ull aa = pack2(av[i]);
                #pragma unroll
                for (int j = 0; j < 4; ++j) dfma(acc[i][j], aa, bv[j]);
            }
        }
        if (has) {
            const int nb = buf ^ 1;
            __syncthreads();
            As[nb][lk + 0][lr] = a0.x; As[nb][lk + 1][lr] = a0.y; As[nb][lk + 2][lr] = a0.z; As[nb][lk + 3][lr] = a0.w;
            As[nb][lk + 0][lr + 64] = a1.x; As[nb][lk + 1][lr + 64] = a1.y; As[nb][lk + 2][lr + 64] = a1.z; As[nb][lk + 3][lr + 64] = a1.w;
            Bs[nb][lk + 0][lr] = b0.x; Bs[nb][lk + 1][lr] = b0.y; Bs[nb][lk + 2][lr] = b0.z; Bs[nb][lk + 3][lr] = b0.w;
            Bs[nb][lk + 0][lr + 64] = b1.x; Bs[nb][lk + 1][lr + 64] = b1.y; Bs[nb][lk + 2][lr + 64] = b1.z; Bs[nb][lk + 3][lr + 64] = b1.w;
            __syncthreads();
        }
    }

    #pragma unroll
    for (int i = 0; i < 8; ++i) {
        float* crow = C + (size_t)(m0 + ty * 8 + i) * ldc + n0 + tx * 8;
        #pragma unroll
        for (int j = 0; j < 4; ++j) {
            float lo = __uint_as_float((unsigned)(acc[i][j] & 0xffffffffu));
            float hi = __uint_as_float((unsigned)(acc[i][j] >> 32));
            if (bias) {
                int n = n0 + tx * 8 + 2 * j;
                lo += bias[n]; hi += bias[n + 1];
            }
            ((float2*)crow)[j] = make_float2(lo, hi);
        }
    }
}

__global__ __launch_bounds__(256) void g1_kernel(const float* __restrict__ wup,
                                                 const float* __restrict__ bup) {
    gemm_body(g_cn2, EE, wup, EE, g_gv, 2 * DFF, 0, 64, bup);
}

__global__ __launch_bounds__(256) void g2_kernel(const float* __restrict__ wdown) {
    gemm_body(g_f, DFF, wdown, DFF, g_part[blockIdx.z], EE, (int)blockIdx.z * 512, 32, nullptr);
}

__global__ __launch_bounds__(256) void k_act() {
    int idx = blockIdx.x * 256 + threadIdx.x;  // 0..262143
    int m = idx >> 10, d = (idx & 1023) << 2;
    const float* row = g_gv + (size_t)m * (2 * DFF);
    float4 g = *(const float4*)(row + d);
    float4 v = *(const float4*)(row + DFF + d);
    float4 f;
    f.x = __sinf(g.x) * v.x; f.y = __sinf(g.y) * v.y;
    f.z = __sinf(g.z) * v.z; f.w = __sinf(g.w) * v.w;
    *(float4*)(g_f + (size_t)m * DFF + d) = f;
}

__global__ __launch_bounds__(256) void k_red(float* __restrict__ out,
                                             const float* __restrict__ bdown, int step) {
    int idx = blockIdx.x * 256 + threadIdx.x;  // 0..65535
    int m = idx >> 8, e = (idx & 255) << 2;
    size_t off = (size_t)m * EE + e;
    float4 s = *(const float4*)(g_part[0] + off);
    #pragma unroll
    for (int p = 1; p < 8; ++p) {
        float4 v = *(const float4*)(g_part[p] + off);
        s.x += v.x; s.y += v.y; s.z += v.z; s.w += v.w;
    }
    float4 bd = *(const float4*)(bdown + e);
    float4 r2 = *(const float4*)(g_res2 + off);
    s.x += bd.x + r2.x; s.y += bd.y + r2.y;
    s.z += bd.z + r2.z; s.w += bd.w + r2.w;
    int b = m >> 6, t = m & 63;
    if (t < 32)
        *(float4*)(out + ((size_t)b * TT + step * 32 + t) * EE + e) = s;
    else
        *(float4*)(g_proc[(step + 1) & 1] + off) = s;
}

extern "C" void kernel_launch(void* const* d_in, const int* in_sizes, int n_in,
                              void* d_out, int out_size) {
    const float* x     = (const float*)d_in[0];
    const float* ln1_w = (const float*)d_in[1];
    const float* ln1_b = (const float*)d_in[2];
    const float* wfft1 = (const float*)d_in[3];
    const float* wfft2 = (const float*)d_in[4];
    const float* ln2_w = (const float*)d_in[5];
    const float* ln2_b = (const float*)d_in[6];
    const float* w_up  = (const float*)d_in[7];
    const float* b_up  = (const float*)d_in[8];
    const float* w_dn  = (const float*)d_in[9];
    const float* b_dn  = (const float*)d_in[10];
    float* out = (float*)d_out;

    k_init_W<<<1, 256>>>(wfft1, wfft2);
    k_init_prev<<<512, 256>>>(x);
    for (int step = 0; step < NSTEPS; ++step) {
        k_pre<<<64, 128>>>(x, step);
        k_fft<<<dim3(8, 4), 128>>>(x, ln1_w, ln1_b, step);
        k_ln2<<<64, 128>>>(ln2_w, ln2_b);
        g1_kernel<<<dim3(64, 2), 256>>>(w_up, b_up);
        k_act<<<1024, 256>>>();
        g2_kernel<<<dim3(8, 2, 8), 256>>>(w_dn);
        k_red<<<256, 256>>>(out, b_dn, step);
    }
}

// round 4
// speedup vs baseline: 2.0453x; 2.0453x over previous
#include <cuda_runtime.h>
#include <cuda_bf16.h>
#include <cstdint>

typedef unsigned long long ull;

#define TTX 4096
#define EEX 1024
#define NSTEPS 128
#define NROWSX 256
#define SMEM_BYTES 81920

// ---------------- device scratch ----------------
__device__ float g_W[64 * 64];
__device__ float g_proc[2][NROWSX * EEX];
__device__ float g_res2[NROWSX * EEX];
__device__ float g_gv[NROWSX * 8192];
__device__ float g_part[8][NROWSX * EEX];
__device__ float g_mu1[NROWSX];
__device__ float g_r1[NROWSX];
__device__ ull g_wup_hi[2097152], g_wup_lo[2097152];   // [8192 x 1024] bf16
__device__ ull g_wdn_hi[1048576], g_wdn_lo[1048576];   // [1024 x 4096] bf16
__device__ ull g_a1hi[65536],    g_a1lo[65536];        // [256 x 1024]  bf16
__device__ ull g_fhi[262144],    g_flo[262144];        // [256 x 4096]  bf16

// ---------------- helpers ----------------
__device__ __forceinline__ uint32_t s2u(const void* p) {
    uint32_t a;
    asm("{ .reg .u64 t; cvta.to.shared.u64 t, %1; cvt.u32.u64 %0, t; }" : "=r"(a) : "l"(p));
    return a;
}
__device__ __forceinline__ void cvt_hilo(float x, unsigned short& h, unsigned short& l) {
    __nv_bfloat16 bh = __float2bfloat16_rn(x);
    float r = x - __bfloat162float(bh);
    __nv_bfloat16 bl = __float2bfloat16_rn(r);
    h = __bfloat16_as_ushort(bh);
    l = __bfloat16_as_ushort(bl);
}
__device__ __forceinline__ void ldm4(uint32_t* r, uint32_t addr) {
    asm volatile("ldmatrix.sync.aligned.m8n8.x4.shared.b16 {%0,%1,%2,%3}, [%4];"
        : "=r"(r[0]), "=r"(r[1]), "=r"(r[2]), "=r"(r[3]) : "r"(addr));
}
__device__ __forceinline__ void mma16816(float* c, const uint32_t* a, const uint32_t* b) {
    asm volatile("mma.sync.aligned.m16n8k16.row.col.f32.bf16.bf16.f32 "
        "{%0,%1,%2,%3}, {%4,%5,%6,%7}, {%8,%9}, {%0,%1,%2,%3};"
        : "+f"(c[0]), "+f"(c[1]), "+f"(c[2]), "+f"(c[3])
        : "r"(a[0]), "r"(a[1]), "r"(a[2]), "r"(a[3]), "r"(b[0]), "r"(b[1]));
}

// ---------------- init kernels ----------------
__global__ void k_init_W(const float* __restrict__ wf1, const float* __restrict__ wf2) {
    for (int id = threadIdx.x; id < 64 * 64; id += blockDim.x) {
        int t = id >> 6, tp = id & 63;
        float s = 0.f;
        #pragma unroll
        for (int u = 0; u < 48; ++u) s += wf2[t * 48 + u] * wf1[u * 64 + tp];
        g_W[id] = s;
    }
}

__global__ void k_init_prev(const float* __restrict__ x) {
    int idx = blockIdx.x * blockDim.x + threadIdx.x;  // 0..131071
    int b = idx >> 15, rem = idx & 32767;
    int r = rem >> 10, e = rem & 1023;
    g_proc[0][(size_t)((b << 6) + 32 + r) * EEX + e] = x[((size_t)b * TTX + r) * EEX + e];
}

__global__ __launch_bounds__(256) void k_conv(const float* __restrict__ wup,
                                              const float* __restrict__ wdn) {
    int i = blockIdx.x * 256 + threadIdx.x;  // 0..3145727 float4 groups
    const float4* src; ull *hi, *lo; int off;
    if (i < 2097152) { src = (const float4*)wup; hi = g_wup_hi; lo = g_wup_lo; off = i; }
    else             { src = (const float4*)wdn; hi = g_wdn_hi; lo = g_wdn_lo; off = i - 2097152; }
    float4 v = src[off];
    unsigned short h0, l0, h1, l1, h2, l2, h3, l3;
    cvt_hilo(v.x, h0, l0); cvt_hilo(v.y, h1, l1);
    cvt_hilo(v.z, h2, l2); cvt_hilo(v.w, h3, l3);
    hi[off] = (ull)h0 | ((ull)h1 << 16) | ((ull)h2 << 32) | ((ull)h3 << 48);
    lo[off] = (ull)l0 | ((ull)l1 << 16) | ((ull)l2 << 32) | ((ull)l3 << 48);
}

// ---------------- LN1 stats ----------------
__global__ __launch_bounds__(128) void k_pre(const float* __restrict__ x, int step) {
    int warp = threadIdx.x >> 5, lane = threadIdx.x & 31;
    int m = blockIdx.x * 4 + warp;
    int b = m >> 6, t = m & 63;
    const float* ptr = nullptr;
    if (t < 32) ptr = g_proc[step & 1] + (size_t)((b << 6) + 32 + t) * EEX;
    else { int g = step * 32 + t; if (g < TTX) ptr = x + ((size_t)b * TTX + g) * EEX; }
    float sum = 0.f, sq = 0.f;
    if (ptr) for (int e = lane * 4; e < EEX; e += 128) {
        float4 v = *(const float4*)(ptr + e);
        sum += v.x + v.y + v.z + v.w;
        sq += v.x * v.x + v.y * v.y + v.z * v.z + v.w * v.w;
    }
    #pragma unroll
    for (int off = 16; off; off >>= 1) {
        sum += __shfl_xor_sync(~0u, sum, off);
        sq  += __shfl_xor_sync(~0u, sq, off);
    }
    if (lane == 0) {
        float mu = sum * (1.f / 1024.f);
        g_mu1[m] = mu;
        g_r1[m] = rsqrtf(sq * (1.f / 1024.f) - mu * mu + 1e-5f);
    }
}

// ---------------- fft mix + residual ----------------
__global__ __launch_bounds__(256) void k_fft(const float* __restrict__ x,
                                             const float* __restrict__ w1,
                                             const float* __restrict__ b1, int step) {
    __shared__ float sW[64][68];
    __shared__ float scn[64][68];
    int b = blockIdx.y, e0 = blockIdx.x * 64;
    int tid = threadIdx.x;
    for (int i = tid; i < 4096; i += 256) sW[i >> 6][i & 63] = g_W[i];
    const float* prev = g_proc[step & 1];
    const float* xb = x + (size_t)b * TTX * EEX;
    #pragma unroll
    for (int it = 0; it < 16; ++it) {
        int idx = it * 256 + tid;
        int tp = idx >> 6, el = idx & 63, e = e0 + el;
        float v;
        if (tp < 32) v = prev[(size_t)((b << 6) + 32 + tp) * EEX + e];
        else { int gg = step * 32 + tp; v = (gg < TTX) ? xb[(size_t)gg * EEX + e] : 0.f; }
        scn[el][tp] = (v - g_mu1[(b << 6) + tp]) * g_r1[(b << 6) + tp] * w1[e] + b1[e];
    }
    __syncthreads();
    int el = tid & 63, tq = tid >> 6;
    float4 cn[16];
    #pragma unroll
    for (int q = 0; q < 16; ++q) cn[q] = *(const float4*)&scn[el][q * 4];
    #pragma unroll
    for (int ti = 0; ti < 16; ++ti) {
        int t = tq * 16 + ti;
        float acc = 0.f;
        #pragma unroll
        for (int q = 0; q < 16; ++q) {
            float4 w = *(const float4*)&sW[t][q * 4];
            acc += w.x * cn[q].x + w.y * cn[q].y + w.z * cn[q].z + w.w * cn[q].w;
        }
        int gg = step * 32 + t;
        float cv = (gg < TTX) ? xb[(size_t)gg * EEX + e0 + el] : 0.f;
        g_res2[(size_t)((b << 6) + t) * EEX + e0 + el] = acc + cv;
    }
}

// ---------------- LN2 -> cn2 hi/lo ----------------
__global__ __launch_bounds__(128) void k_ln2(const float* __restrict__ w,
                                             const float* __restrict__ bb) {
    int warp = threadIdx.x >> 5, lane = threadIdx.x & 31;
    int m = blockIdx.x * 4 + warp;
    const float* row = g_res2 + (size_t)m * EEX;
    float sum = 0.f, sq = 0.f;
    for (int e = lane * 4; e < EEX; e += 128) {
        float4 v = *(const float4*)(row + e);
        sum += v.x + v.y + v.z + v.w;
        sq += v.x * v.x + v.y * v.y + v.z * v.z + v.w * v.w;
    }
    #pragma unroll
    for (int off = 16; off; off >>= 1) {
        sum += __shfl_xor_sync(~0u, sum, off);
        sq  += __shfl_xor_sync(~0u, sq, off);
    }
    float mu = sum * (1.f / 1024.f);
    float r = rsqrtf(sq * (1.f / 1024.f) - mu * mu + 1e-5f);
    for (int e = lane * 4; e < EEX; e += 128) {
        float4 v = *(const float4*)(row + e);
        float4 ww = *(const float4*)(w + e);
        float4 bv = *(const float4*)(bb + e);
        float o0 = (v.x - mu) * r * ww.x + bv.x;
        float o1 = (v.y - mu) * r * ww.y + bv.y;
        float o2 = (v.z - mu) * r * ww.z + bv.z;
        float o3 = (v.w - mu) * r * ww.w + bv.w;
        unsigned short h0, l0, h1, l1, h2, l2, h3, l3;
        cvt_hilo(o0, h0, l0); cvt_hilo(o1, h1, l1);
        cvt_hilo(o2, h2, l2); cvt_hilo(o3, h3, l3);
        int q = m * 256 + (e >> 2);
        g_a1hi[q] = (ull)h0 | ((ull)h1 << 16) | ((ull)h2 << 32) | ((ull)h3 << 48);
        g_a1lo[q] = (ull)l0 | ((ull)l1 << 16) | ((ull)l2 << 32) | ((ull)l3 << 48);
    }
}

// ---------------- mma.sync GEMM core ----------------
struct MArgs {
    const __nv_bfloat16 *Ahi, *Alo, *Bhi, *Blo;
    int ldA, ldB, NC;
};

// smem per buffer: Ah@0, Al@10240, Bh@20480, Bl@30720 (128 rows x 32 bf16, stride 80B)
__device__ __forceinline__ void load_chunk(uint32_t sbase, const MArgs& a, int kof, int tid) {
    #pragma unroll
    for (int it = 0; it < 8; ++it) {
        int idx = it * 256 + tid;
        int tile = idx >> 9, r = (idx >> 2) & 127, c4 = idx & 3;
        const __nv_bfloat16* g; int ld;
        if (tile == 0)      { g = a.Ahi; ld = a.ldA; }
        else if (tile == 1) { g = a.Alo; ld = a.ldA; }
        else if (tile == 2) { g = a.Bhi; ld = a.ldB; }
        else                { g = a.Blo; ld = a.ldB; }
        uint32_t dst = sbase + (uint32_t)(tile * 10240 + r * 80 + c4 * 16);
        asm volatile("cp.async.cg.shared.global [%0], [%1], 16;"
            :: "r"(dst), "l"((const void*)(g + (size_t)r * ld + kof + c4 * 8)) : "memory");
    }
    asm volatile("cp.async.commit_group;" ::: "memory");
}

__device__ void mma_main(char* smem, const MArgs& a, float acc[4][4][4]) {
    uint32_t sbase = s2u(smem);
    int tid = threadIdx.x, lane = tid & 31, wid = tid >> 5;
    int wm = (wid >> 2) * 64, wn = (wid & 3) * 32;
    uint32_t aoff = (uint32_t)((wm + (lane & 15)) * 80 + (lane >> 4) * 16);
    uint32_t boff = (uint32_t)((wn + ((lane >> 4) << 3) + (lane & 7)) * 80 + ((lane >> 3) & 1) * 16);

    load_chunk(sbase, a, 0, tid);
    if (a.NC > 1) load_chunk(sbase + 40960u, a, 32, tid);

    for (int c = 0; c < a.NC; ++c) {
        if (c + 1 < a.NC) asm volatile("cp.async.wait_group 1;" ::: "memory");
        else              asm volatile("cp.async.wait_group 0;" ::: "memory");
        __syncthreads();
        uint32_t sb = sbase + (uint32_t)(c & 1) * 40960u;
        #pragma unroll
        for (int ks = 0; ks < 2; ++ks) {
            uint32_t ko = (uint32_t)ks * 32u;
            uint32_t ah[4][4], al[4][4], bh[2][4], bl[2][4];
            #pragma unroll
            for (int mi = 0; mi < 4; ++mi) {
                ldm4(ah[mi], sb + aoff + mi * 1280 + ko);
                ldm4(al[mi], sb + 10240 + aoff + mi * 1280 + ko);
            }
            #pragma unroll
            for (int p = 0; p < 2; ++p) {
                ldm4(bh[p], sb + 20480 + boff + p * 1280 + ko);
                ldm4(bl[p], sb + 30720 + boff + p * 1280 + ko);
            }
            #pragma unroll
            for (int mi = 0; mi < 4; ++mi)
                #pragma unroll
                for (int ni = 0; ni < 4; ++ni) {
                    float* cc = acc[mi][ni];
                    const uint32_t* Bh = &bh[ni >> 1][(ni & 1) * 2];
                    const uint32_t* Bl = &bl[ni >> 1][(ni & 1) * 2];
                    mma16816(cc, ah[mi], Bh);
                    mma16816(cc, ah[mi], Bl);
                    mma16816(cc, al[mi], Bh);
                }
        }
        __syncthreads();
        if (c + 2 < a.NC) load_chunk(sb, a, (c + 2) * 32, tid);
    }
}

// ---------------- GEMM1: gv = cn2 @ w_up^T + b_up ----------------
__global__ __launch_bounds__(256, 1) void g1_kernel(const float* __restrict__ bup) {
    extern __shared__ char smem[];
    int n0 = blockIdx.x * 128, m0 = blockIdx.y * 128;
    MArgs a;
    a.Ahi = (const __nv_bfloat16*)g_a1hi + (size_t)m0 * 1024;
    a.Alo = (const __nv_bfloat16*)g_a1lo + (size_t)m0 * 1024;
    a.Bhi = (const __nv_bfloat16*)g_wup_hi + (size_t)n0 * 1024;
    a.Blo = (const __nv_bfloat16*)g_wup_lo + (size_t)n0 * 1024;
    a.ldA = 1024; a.ldB = 1024; a.NC = 32;
    float acc[4][4][4] = {};
    mma_main(smem, a, acc);

    int lane = threadIdx.x & 31, wid = threadIdx.x >> 5;
    int wm = (wid >> 2) * 64, wn = (wid & 3) * 32;
    #pragma unroll
    for (int mi = 0; mi < 4; ++mi)
        #pragma unroll
        for (int ni = 0; ni < 4; ++ni) {
            int r0 = m0 + wm + mi * 16 + (lane >> 2);
            int cn = n0 + wn + ni * 8 + (lane & 3) * 2;
            float b0v = bup[cn], b1v = bup[cn + 1];
            *(float2*)&g_gv[(size_t)r0 * 8192 + cn] =
                make_float2(acc[mi][ni][0] + b0v, acc[mi][ni][1] + b1v);
            *(float2*)&g_gv[(size_t)(r0 + 8) * 8192 + cn] =
                make_float2(acc[mi][ni][2] + b0v, acc[mi][ni][3] + b1v);
        }
}

// ---------------- activation -> f hi/lo ----------------
__global__ __launch_bounds__(256) void k_act() {
    int i = blockIdx.x * 256 + threadIdx.x;  // 0..262143
    int m = i >> 10, d4 = i & 1023;
    const float* row = g_gv + (size_t)m * 8192;
    float4 g = *(const float4*)(row + d4 * 4);
    float4 v = *(const float4*)(row + 4096 + d4 * 4);
    float f0 = __sinf(g.x) * v.x, f1 = __sinf(g.y) * v.y;
    float f2 = __sinf(g.z) * v.z, f3 = __sinf(g.w) * v.w;
    unsigned short h0, l0, h1, l1, h2, l2, h3, l3;
    cvt_hilo(f0, h0, l0); cvt_hilo(f1, h1, l1);
    cvt_hilo(f2, h2, l2); cvt_hilo(f3, h3, l3);
    size_t q = (size_t)m * 1024 + d4;
    g_fhi[q] = (ull)h0 | ((ull)h1 << 16) | ((ull)h2 << 32) | ((ull)h3 << 48);
    g_flo[q] = (ull)l0 | ((ull)l1 << 16) | ((ull)l2 << 32) | ((ull)l3 << 48);
}

// ---------------- GEMM2: partial = f @ w_down^T (split-K=8) ----------------
__global__ __launch_bounds__(256, 1) void g2_kernel() {
    extern __shared__ char smem[];
    int n0 = blockIdx.x * 128, m0 = blockIdx.y * 128, z = blockIdx.z;
    MArgs a;
    a.Ahi = (const __nv_bfloat16*)g_fhi + (size_t)m0 * 4096 + z * 512;
    a.Alo = (const __nv_bfloat16*)g_flo + (size_t)m0 * 4096 + z * 512;
    a.Bhi = (const __nv_bfloat16*)g_wdn_hi + (size_t)n0 * 4096 + z * 512;
    a.Blo = (const __nv_bfloat16*)g_wdn_lo + (size_t)n0 * 4096 + z * 512;
    a.ldA = 4096; a.ldB = 4096; a.NC = 16;
    float acc[4][4][4] = {};
    mma_main(smem, a, acc);

    int lane = threadIdx.x & 31, wid = threadIdx.x >> 5;
    int wm = (wid >> 2) * 64, wn = (wid & 3) * 32;
    float* dst = g_part[z];
    #pragma unroll
    for (int mi = 0; mi < 4; ++mi)
        #pragma unroll
        for (int ni = 0; ni < 4; ++ni) {
            int r0 = m0 + wm + mi * 16 + (lane >> 2);
            int cn = n0 + wn + ni * 8 + (lane & 3) * 2;
            *(float2*)&dst[(size_t)r0 * 1024 + cn] =
                make_float2(acc[mi][ni][0], acc[mi][ni][1]);
            *(float2*)&dst[(size_t)(r0 + 8) * 1024 + cn] =
                make_float2(acc[mi][ni][2], acc[mi][ni][3]);
        }
}

// ---------------- split-K reduce + b_down + res2 ----------------
__global__ __launch_bounds__(256) void k_red(float* __restrict__ out,
                                             const float* __restrict__ bdown, int step) {
    int idx = blockIdx.x * 256 + threadIdx.x;  // 0..65535
    int m = idx >> 8, e = (idx & 255) << 2;
    size_t off = (size_t)m * EEX + e;
    float4 s = *(const float4*)(g_part[0] + off);
    #pragma unroll
    for (int p = 1; p < 8; ++p) {
        float4 v = *(const float4*)(g_part[p] + off);
        s.x += v.x; s.y += v.y; s.z += v.z; s.w += v.w;
    }
    float4 bd = *(const float4*)(bdown + e);
    float4 r2 = *(const float4*)(g_res2 + off);
    s.x += bd.x + r2.x; s.y += bd.y + r2.y;
    s.z += bd.z + r2.z; s.w += bd.w + r2.w;
    int b = m >> 6, t = m & 63;
    if (t < 32)
        *(float4*)(out + ((size_t)b * TTX + step * 32 + t) * EEX + e) = s;
    else
        *(float4*)(g_proc[(step + 1) & 1] + off) = s;
}

extern "C" void kernel_launch(void* const* d_in, const int* in_sizes, int n_in,
                              void* d_out, int out_size) {
    const float* x     = (const float*)d_in[0];
    const float* ln1_w = (const float*)d_in[1];
    const float* ln1_b = (const float*)d_in[2];
    const float* wfft1 = (const float*)d_in[3];
    const float* wfft2 = (const float*)d_in[4];
    const float* ln2_w = (const float*)d_in[5];
    const float* ln2_b = (const float*)d_in[6];
    const float* w_up  = (const float*)d_in[7];
    const float* b_up  = (const float*)d_in[8];
    const float* w_dn  = (const float*)d_in[9];
    const float* b_dn  = (const float*)d_in[10];
    float* out = (float*)d_out;

    cudaFuncSetAttribute(g1_kernel, cudaFuncAttributeMaxDynamicSharedMemorySize, SMEM_BYTES);
    cudaFuncSetAttribute(g2_kernel, cudaFuncAttributeMaxDynamicSharedMemorySize, SMEM_BYTES);

    k_init_W<<<1, 256>>>(wfft1, wfft2);
    k_init_prev<<<512, 256>>>(x);
    k_conv<<<12288, 256>>>(w_up, w_dn);

    for (int step = 0; step < NSTEPS; ++step) {
        k_pre<<<64, 128>>>(x, step);
        k_fft<<<dim3(16, 4), 256>>>(x, ln1_w, ln1_b, step);
        k_ln2<<<64, 128>>>(ln2_w, ln2_b);
        g1_kernel<<<dim3(64, 2), 256, SMEM_BYTES>>>(b_up);
        k_act<<<1024, 256>>>();
        g2_kernel<<<dim3(8, 2, 8), 256, SMEM_BYTES>>>();
        k_red<<<256, 256>>>(out, b_dn, step);
    }
}